// round 1
// baseline (speedup 1.0000x reference)
#include <cuda_runtime.h>
#include <cstdint>

#define BT     16384      // B*T = 64*256
#define TT     256
#define NB     64
#define DIN    5881
#define DM     64
#define DI     128
#define NS     16
#define DTR    4

// ---------------- scratch (device globals; no allocation allowed) ----------------
__device__ float g_z[BT * DM];        // encoder output            [i, 64]
__device__ float g_x[BT * DI];        // x branch of in-proj       [i, 128]
__device__ float g_gates[BT * DI];    // silu(gate)                [i, 128]
__device__ float g_xconv[BT * DI];    // silu(conv(x))             [i, 128]
__device__ float g_dt[BT * DI];       // softplus(dt)              [i, 128]
__device__ float g_B[BT * NS];        // [i, 16]
__device__ float g_C[BT * NS];        // [i, 16]
__device__ float g_ybar[NB * DI];     // mean_t of mamba y         [b, 128]

// ---------------- fast math helpers (MUFU-based) ----------------
__device__ __forceinline__ float fexp2(float x) {
    float y; asm("ex2.approx.f32 %0, %1;" : "=f"(y) : "f"(x)); return y;
}
__device__ __forceinline__ float fexp(float x) { return fexp2(x * 1.4426950408889634f); }
__device__ __forceinline__ float flog2(float x) {
    float y; asm("lg2.approx.f32 %0, %1;" : "=f"(y) : "f"(x)); return y;
}
__device__ __forceinline__ float fsilu(float x) {
    return __fdividef(x, 1.f + fexp(-x));
}
__device__ __forceinline__ float fsoftplus(float x) {
    return fmaxf(x, 0.f) + 0.6931471805599453f * flog2(1.f + fexp(-fabsf(x)));
}

// ================= K1: encoder GEMM  z[i,m] = sum_f in[i,f]*We[m,f] + be[m] =====
// BM=128, BN=64, BK=32, 256 threads, thread tile 8x4
__global__ void k1_encoder(const float* __restrict__ in,
                           const float* __restrict__ We,
                           const float* __restrict__ be) {
    __shared__ float As[128][33];
    __shared__ float Bs[64][33];
    const int tid  = threadIdx.x;
    const int row0 = blockIdx.x * 128;
    const int tx = tid & 15;       // 16 col groups * 4
    const int ty = tid >> 4;       // 16 row groups * 8
    const int kk0 = tid & 31;
    const int mA  = tid >> 5;      // 0..7

    float acc[8][4];
#pragma unroll
    for (int r = 0; r < 8; r++)
#pragma unroll
        for (int j = 0; j < 4; j++) acc[r][j] = 0.f;

    for (int kb = 0; kb < DIN; kb += 32) {
        __syncthreads();
        const int k = kb + kk0;
        const bool kin = (k < DIN);
#pragma unroll
        for (int i = 0; i < 16; i++) {
            const int m = mA + i * 8;
            As[m][kk0] = kin ? in[(row0 + m) * DIN + k] : 0.f;
        }
#pragma unroll
        for (int i = 0; i < 8; i++) {
            const int j = mA + i * 8;
            Bs[j][kk0] = kin ? We[j * DIN + k] : 0.f;
        }
        __syncthreads();
#pragma unroll
        for (int kk = 0; kk < 32; kk++) {
            float a[8], bv[4];
#pragma unroll
            for (int r = 0; r < 8; r++) a[r] = As[ty * 8 + r][kk];
#pragma unroll
            for (int j = 0; j < 4; j++) bv[j] = Bs[tx * 4 + j][kk];
#pragma unroll
            for (int r = 0; r < 8; r++)
#pragma unroll
                for (int j = 0; j < 4; j++) acc[r][j] += a[r] * bv[j];
        }
    }
#pragma unroll
    for (int r = 0; r < 8; r++) {
        const int row = row0 + ty * 8 + r;
#pragma unroll
        for (int j = 0; j < 4; j++) {
            const int col = tx * 4 + j;
            g_z[row * DM + col] = acc[r][j] + be[col];
        }
    }
}

// ================= K2: in-proj  xz[i,c] = sum_m z[i,m]*Win[c,m] =================
// BM=8 rows per block, 256 threads (one per output col), silu applied to gate half
__global__ void k2_inproj(const float* __restrict__ Win) {
    __shared__ float zs[8][64];
    const int tid  = threadIdx.x;
    const int row0 = blockIdx.x * 8;
#pragma unroll
    for (int it = 0; it < 2; it++) {
        const int f = tid + it * 256;
        zs[f >> 6][f & 63] = g_z[(row0 + (f >> 6)) * DM + (f & 63)];
    }
    __syncthreads();
    const int c = tid;   // 0..255
    float acc[8];
#pragma unroll
    for (int r = 0; r < 8; r++) acc[r] = 0.f;
#pragma unroll 8
    for (int k = 0; k < 64; k++) {
        const float w = Win[c * 64 + k];
#pragma unroll
        for (int r = 0; r < 8; r++) acc[r] += zs[r][k] * w;
    }
#pragma unroll
    for (int r = 0; r < 8; r++) {
        const int i = row0 + r;
        if (c < DI) g_x[i * DI + c] = acc[r];
        else        g_gates[i * DI + (c - DI)] = fsilu(acc[r]);
    }
}

// ================= K3: causal depthwise conv (k=4) + silu =======================
__global__ void k3_conv(const float* __restrict__ cw, const float* __restrict__ cb) {
    const int gid = blockIdx.x * 256 + threadIdx.x;   // over BT*128
    const int d = gid & 127;
    const int i = gid >> 7;
    const int t = i & 255;
    float s = cb[d];
#pragma unroll
    for (int k = 0; k < 4; k++) {
        const int tk = t + k - 3;
        if (tk >= 0) s += g_x[(i - t + tk) * DI + d] * cw[d * 4 + k];
    }
    g_xconv[gid] = fsilu(s);
}

// ================= K4: x-proj (36 outs) + dt path + write B/C ===================
// 128 threads, 16 rows per block
__global__ void k4_xproj(const float* __restrict__ Wx,
                         const float* __restrict__ Wdt,
                         const float* __restrict__ bdt) {
    __shared__ float xs[16][129];
    __shared__ float Wxs[36][132];
    __shared__ float dbl[16][40];
    __shared__ float Wdts[DI * DTR];
    __shared__ float bdts[DI];
    const int tid  = threadIdx.x;
    const int row0 = blockIdx.x * 16;

    for (int f = tid; f < 36 * 128; f += 128) Wxs[f >> 7][f & 127] = Wx[f];
    for (int f = tid; f < DI * DTR; f += 128) Wdts[f] = Wdt[f];
    if (tid < DI) bdts[tid] = bdt[tid];
    for (int f = tid; f < 16 * 128; f += 128)
        xs[f >> 7][f & 127] = g_xconv[(row0 + (f >> 7)) * DI + (f & 127)];
    __syncthreads();

    const int r  = tid >> 3;   // 0..15
    const int jg = tid & 7;    // 0..7
    float acc[5];
#pragma unroll
    for (int q = 0; q < 5; q++) acc[q] = 0.f;
#pragma unroll 4
    for (int k = 0; k < 128; k++) {
        const float xv = xs[r][k];
#pragma unroll
        for (int q = 0; q < 5; q++) {
            const int j = jg + q * 8;
            if (j < 36) acc[q] += xv * Wxs[j][k];
        }
    }
#pragma unroll
    for (int q = 0; q < 5; q++) {
        const int j = jg + q * 8;
        if (j < 36) dbl[r][j] = acc[q];
    }
    __syncthreads();

    // dt = softplus(dbl[:, :4] @ Wdt^T + bdt)
    {
        const int d = tid;  // 0..127
        const float w0 = Wdts[d * 4 + 0], w1 = Wdts[d * 4 + 1];
        const float w2 = Wdts[d * 4 + 2], w3 = Wdts[d * 4 + 3];
        const float bb = bdts[d];
#pragma unroll
        for (int rr = 0; rr < 16; rr++) {
            float v = bb + dbl[rr][0] * w0 + dbl[rr][1] * w1
                         + dbl[rr][2] * w2 + dbl[rr][3] * w3;
            g_dt[(row0 + rr) * DI + d] = fsoftplus(v);
        }
    }
    // B, C
    for (int f = tid; f < 16 * 32; f += 128) {
        const int rr = f >> 5;
        const int c  = f & 31;
        const float v = dbl[rr][4 + c];
        if (c < 16) g_B[(row0 + rr) * NS + c] = v;
        else        g_C[(row0 + rr) * NS + (c - 16)] = v;
    }
}

// ================= K5: selective scan, 2 threads per (b,d), 8 states each =======
// grid 128 (b * 2 halves of d), 128 threads
__global__ void k5_scan(const float* __restrict__ A_log,
                        const float* __restrict__ Dskip) {
    __shared__ float sBC[64 * 32];    // [t][0..15]=B, [t][16..31]=C
    const int tid = threadIdx.x;
    const int b     = blockIdx.x >> 1;
    const int dbase = (blockIdx.x & 1) * 64;
    const int dl   = tid >> 1;
    const int half = tid & 1;
    const int d = dbase + dl;

    float c2[8];
#pragma unroll
    for (int n = 0; n < 8; n++)
        c2[n] = -fexp(A_log[d * NS + half * 8 + n]) * 1.4426950408889634f;
    const float dsk = Dskip[d];

    float h[8];
#pragma unroll
    for (int n = 0; n < 8; n++) h[n] = 0.f;
    float ys = 0.f;

    for (int tc = 0; tc < 4; tc++) {
        __syncthreads();
#pragma unroll
        for (int it = 0; it < 16; it++) {
            const int f  = tid + it * 128;
            const int tt = f >> 5;
            const int c  = f & 31;
            const int i  = b * TT + tc * 64 + tt;
            sBC[f] = (c < 16) ? g_B[i * NS + c] : g_C[i * NS + (c - 16)];
        }
        __syncthreads();
        for (int t = 0; t < 64; t++) {
            const int base = (b * TT + tc * 64 + t) * DI + d;
            const float dt = g_dt[base];
            const float xc = g_xconv[base];
            const float gg = g_gates[base];
            const float dtx = dt * xc;
            float yp = 0.f;
            const float* bc = &sBC[t * 32 + half * 8];
#pragma unroll
            for (int n = 0; n < 8; n++) {
                const float e = fexp2(dt * c2[n]);
                h[n] = e * h[n] + dtx * bc[n];
                yp += h[n] * bc[16 + n];
            }
            const float yo = yp + __shfl_xor_sync(0xffffffffu, yp, 1);
            ys += (yo + dsk * xc) * gg;
        }
    }
    if (half == 0) g_ybar[b * DI + d] = ys * (1.f / 256.f);
}

// ================= K6: heads — one block per batch element ======================
__global__ void k6_heads(const float* __restrict__ Wout,
                         const float* __restrict__ Wfc, const float* __restrict__ bfc,
                         const float* __restrict__ Wmu, const float* __restrict__ bmu,
                         const float* __restrict__ Wsig, const float* __restrict__ bsig,
                         float* __restrict__ out) {
    __shared__ float yb[DI], ev[DM], xsm[DI];
    const int b = blockIdx.x, tid = threadIdx.x;
    yb[tid] = g_ybar[b * DI + tid];
    __syncthreads();
    if (tid < DM) {
        float s = 0.f;
#pragma unroll 4
        for (int dd = 0; dd < DI; dd++) s += yb[dd] * Wout[tid * DI + dd];
        ev[tid] = s;
    }
    __syncthreads();
    {
        float v = bfc[tid];
#pragma unroll 4
        for (int m = 0; m < DM; m++) v += ev[m] * Wfc[tid * DM + m];
        const float t = tanhf(v);
        const float x = (t > 0.f) ? t : expm1f(t);
        xsm[tid] = x;
        out[b * DI + tid] = x;
    }
    __syncthreads();
    for (int o = tid; o < 256; o += 128) {
        float sm = bmu[o], sg = bsig[o];
#pragma unroll 4
        for (int l = 0; l < DI; l++) {
            const float xv = xsm[l];
            sm += xv * Wmu[o * DI + l];
            sg += xv * Wsig[o * DI + l];
        }
        out[NB * DI + b * 256 + o] = sm;
        const float e2 = (sg > 0.f) ? sg : expm1f(sg);
        out[NB * DI + NB * 256 + b * 256 + o] = e2 + 1.f + 1e-14f;
    }
}

// ================================================================================
extern "C" void kernel_launch(void* const* d_in, const int* in_sizes, int n_in,
                              void* d_out, int out_size) {
    const float* input  = (const float*)d_in[0];
    const float* W_enc  = (const float*)d_in[1];
    const float* b_enc  = (const float*)d_in[2];
    const float* W_in   = (const float*)d_in[3];
    const float* conv_w = (const float*)d_in[4];
    const float* conv_b = (const float*)d_in[5];
    const float* W_x    = (const float*)d_in[6];
    const float* W_dt   = (const float*)d_in[7];
    const float* b_dt   = (const float*)d_in[8];
    const float* A_log  = (const float*)d_in[9];
    const float* D_skip = (const float*)d_in[10];
    const float* W_out  = (const float*)d_in[11];
    const float* W_fc   = (const float*)d_in[12];
    const float* b_fc   = (const float*)d_in[13];
    const float* W_mu   = (const float*)d_in[14];
    const float* b_mu   = (const float*)d_in[15];
    const float* W_sig  = (const float*)d_in[16];
    const float* b_sig  = (const float*)d_in[17];
    float* out = (float*)d_out;

    k1_encoder<<<BT / 128, 256>>>(input, W_enc, b_enc);
    k2_inproj<<<BT / 8, 256>>>(W_in);
    k3_conv<<<(BT * DI) / 256, 256>>>(conv_w, conv_b);
    k4_xproj<<<BT / 16, 128>>>(W_x, W_dt, b_dt);
    k5_scan<<<NB * 2, 128>>>(A_log, D_skip);
    k6_heads<<<NB, 128>>>(W_out, W_fc, b_fc, W_mu, b_mu, W_sig, b_sig, out);
}

// round 6
// speedup vs baseline: 1.1846x; 1.1846x over previous
#include <cuda_runtime.h>
#include <cstdint>

#define BT     16384
#define TT     256
#define NB     64
#define DIN    5881
#define DINP   5888
#define DM     64
#define DI     128
#define NS     16
#define NIT    184        // ceil(5881/32)
#define LOG2E  1.4426950408889634f

typedef unsigned short ushortT;
typedef unsigned int uintT;

__device__ float g_z[BT * DM];
__device__ float g_x[BT * DI];
__device__ float g_gates[BT * DI];
__device__ float g_xconv[BT * DI];
__device__ float g_dt[BT * DI];
__device__ float g_B[BT * NS];
__device__ float g_C[BT * NS];
__device__ float g_ybar[NB * DI];
__device__ ushortT g_Bh[DM * DINP];
__device__ ushortT g_Bl[DM * DINP];

__device__ __forceinline__ float fexp2(float x) {
    float y; asm("ex2.approx.f32 %0, %1;" : "=f"(y) : "f"(x)); return y;
}
__device__ __forceinline__ float fexp(float x) { return fexp2(x * LOG2E); }
__device__ __forceinline__ float flog2(float x) {
    float y; asm("lg2.approx.f32 %0, %1;" : "=f"(y) : "f"(x)); return y;
}
__device__ __forceinline__ float fsilu(float x) { return __fdividef(x, 1.f + fexp(-x)); }
__device__ __forceinline__ float fsoftplus(float x) {
    return fmaxf(x, 0.f) + 0.6931471805599453f * flog2(1.f + fexp(-fabsf(x)));
}
__device__ __forceinline__ uintT cvt2(float lo, float hi) {
    uintT r; asm("cvt.rn.bf16x2.f32 %0, %1, %2;" : "=r"(r) : "f"(hi), "f"(lo)); return r;
}
__device__ __forceinline__ void ldsm4(uintT* r, const ushortT* p) {
    uintT a = (uintT)__cvta_generic_to_shared(p);
    asm volatile("ldmatrix.sync.aligned.m8n8.x4.shared.b16 {%0,%1,%2,%3}, [%4];"
        : "=r"(r[0]), "=r"(r[1]), "=r"(r[2]), "=r"(r[3]) : "r"(a));
}
__device__ __forceinline__ void mma16816(float* c, const uintT* a, uintT b0, uintT b1) {
    asm volatile("mma.sync.aligned.m16n8k16.row.col.f32.bf16.bf16.f32 "
        "{%0,%1,%2,%3}, {%4,%5,%6,%7}, {%8,%9}, {%0,%1,%2,%3};"
        : "+f"(c[0]), "+f"(c[1]), "+f"(c[2]), "+f"(c[3])
        : "r"(a[0]), "r"(a[1]), "r"(a[2]), "r"(a[3]), "r"(b0), "r"(b1));
}

// ========== K0: repack W_enc -> padded bf16 hi/lo ==========
__global__ void k0_brepack(const float* __restrict__ W) {
    const int gid = blockIdx.x * 256 + threadIdx.x;    // 64*5888
    const int row = gid / DINP, k = gid - row * DINP;
    const float v = (k < DIN) ? W[row * DIN + k] : 0.f;
    const uintT xh = cvt2(v, 0.f);
    const float hf = __uint_as_float(xh << 16);
    g_Bh[gid] = (ushortT)xh;
    g_Bl[gid] = (ushortT)cvt2(v - hf, 0.f);
}

// ========== K1: encoder GEMM via bf16x3 tensor MMA ==========
// C[16384,64] = A[16384,5881] @ W^T. BM=64, BN=64, BK=32, 128 threads (4 warps).
__global__ void __launch_bounds__(128) k1_gemm(const float* __restrict__ A,
                                               const float* __restrict__ be) {
    __shared__ __align__(16) ushortT sAh[64 * 40], sAl[64 * 40];
    __shared__ __align__(16) ushortT sBh[64 * 40], sBl[64 * 40];
    const int tid  = threadIdx.x;
    const int lane = tid & 31, warp = tid >> 5;
    const int row0 = blockIdx.x * 64;
    const int r = tid >> 1, h = tid & 1;       // staging row 0..63, k-half
    const long abase = (long)(row0 + r) * DIN;

    float w[16];
    uint4 vbh0, vbh1, vbl0, vbl1;

    auto loadT = [&](int it) {
        const int kb = it * 32 + 16 * h;
        if (it < NIT - 1) {
#pragma unroll
            for (int j = 0; j < 16; j++) w[j] = A[abase + kb + j];
        } else {
#pragma unroll
            for (int j = 0; j < 16; j++) w[j] = (kb + j < DIN) ? A[abase + kb + j] : 0.f;
        }
        const uint4* ph = (const uint4*)(g_Bh + r * DINP + kb);
        const uint4* pl = (const uint4*)(g_Bl + r * DINP + kb);
        vbh0 = ph[0]; vbh1 = ph[1]; vbl0 = pl[0]; vbl1 = pl[1];
    };
    auto stage = [&]() {
        uintT* dAh = (uintT*)sAh + r * 20 + h * 8;
        uintT* dAl = (uintT*)sAl + r * 20 + h * 8;
#pragma unroll
        for (int j = 0; j < 8; j++) {
            const uintT xh = cvt2(w[2 * j], w[2 * j + 1]);
            const float h0 = __uint_as_float(xh << 16);
            const float h1 = __uint_as_float(xh & 0xffff0000u);
            dAh[j] = xh;
            dAl[j] = cvt2(w[2 * j] - h0, w[2 * j + 1] - h1);
        }
        uint4* dBh = (uint4*)((uintT*)sBh + r * 20 + h * 8);
        uint4* dBl = (uint4*)((uintT*)sBl + r * 20 + h * 8);
        dBh[0] = vbh0; dBh[1] = vbh1; dBl[0] = vbl0; dBl[1] = vbl1;
    };

    float acc[8][4];
#pragma unroll
    for (int j = 0; j < 8; j++)
#pragma unroll
        for (int q = 0; q < 4; q++) acc[j][q] = 0.f;

    const int wr0 = warp * 16;
    loadT(0);
    for (int it = 0; it < NIT; it++) {
        stage();
        __syncthreads();
        if (it < NIT - 1) loadT(it + 1);
#pragma unroll
        for (int s = 0; s < 2; s++) {
            uintT ah[4], al[4], bh[4], bl[4];
            const int aoff = (wr0 + (lane & 15)) * 40 + 16 * s + ((lane >> 4) << 3);
            ldsm4(ah, sAh + aoff);
            ldsm4(al, sAl + aoff);
#pragma unroll
            for (int p = 0; p < 4; p++) {
                const int boff = (16 * p + ((lane >> 4) << 3) + (lane & 7)) * 40
                               + 16 * s + (lane & 8);
                ldsm4(bh, sBh + boff);
                ldsm4(bl, sBl + boff);
                mma16816(acc[2 * p],     ah, bh[0], bh[1]);
                mma16816(acc[2 * p],     ah, bl[0], bl[1]);
                mma16816(acc[2 * p],     al, bh[0], bh[1]);
                mma16816(acc[2 * p + 1], ah, bh[2], bh[3]);
                mma16816(acc[2 * p + 1], ah, bl[2], bl[3]);
                mma16816(acc[2 * p + 1], al, bh[2], bh[3]);
            }
        }
        __syncthreads();
    }
    const int orow = row0 + wr0 + (lane >> 2);
    const int cb = (lane & 3) * 2;
#pragma unroll
    for (int j = 0; j < 8; j++) {
        const int c = 8 * j + cb;
        const float b0 = __ldg(be + c), b1 = __ldg(be + c + 1);
        *(float2*)&g_z[orow * DM + c] = make_float2(acc[j][0] + b0, acc[j][1] + b1);
        *(float2*)&g_z[(orow + 8) * DM + c] = make_float2(acc[j][2] + b0, acc[j][3] + b1);
    }
}

// ========== K2: in-proj + silu(gate) ==========
__global__ void k2_inproj(const float* __restrict__ Win) {
    __shared__ float zs[8][64];
    const int tid = threadIdx.x, row0 = blockIdx.x * 8;
#pragma unroll
    for (int it = 0; it < 2; it++) {
        const int f = tid + it * 256;
        zs[f >> 6][f & 63] = g_z[(row0 + (f >> 6)) * DM + (f & 63)];
    }
    __syncthreads();
    const int c = tid;
    float acc[8];
#pragma unroll
    for (int rr = 0; rr < 8; rr++) acc[rr] = 0.f;
#pragma unroll 8
    for (int k = 0; k < 64; k++) {
        const float wv = Win[c * 64 + k];
#pragma unroll
        for (int rr = 0; rr < 8; rr++) acc[rr] += zs[rr][k] * wv;
    }
#pragma unroll
    for (int rr = 0; rr < 8; rr++) {
        const int i = row0 + rr;
        if (c < DI) g_x[i * DI + c] = acc[rr];
        else        g_gates[i * DI + (c - DI)] = fsilu(acc[rr]);
    }
}

// ========== K3: causal depthwise conv(4) + silu ==========
__global__ void k3_conv(const float* __restrict__ cw, const float* __restrict__ cb) {
    const int gid = blockIdx.x * 256 + threadIdx.x;
    const int d = gid & 127, i = gid >> 7, t = i & 255;
    float s = cb[d];
#pragma unroll
    for (int k = 0; k < 4; k++) {
        const int tk = t + k - 3;
        if (tk >= 0) s += g_x[(i - t + tk) * DI + d] * cw[d * 4 + k];
    }
    g_xconv[gid] = fsilu(s);
}

// ========== K4: x-proj + dt path + B/C ==========
__global__ void k4_xproj(const float* __restrict__ Wx, const float* __restrict__ Wdt,
                         const float* __restrict__ bdt) {
    __shared__ float xs[16][129], Wxs[36][132], dbl[16][40], Wdts[DI * 4], bdts[DI];
    const int tid = threadIdx.x, row0 = blockIdx.x * 16;
    for (int f = tid; f < 36 * 128; f += 128) Wxs[f >> 7][f & 127] = Wx[f];
    for (int f = tid; f < DI * 4; f += 128) Wdts[f] = Wdt[f];
    if (tid < DI) bdts[tid] = bdt[tid];
    for (int f = tid; f < 16 * 128; f += 128)
        xs[f >> 7][f & 127] = g_xconv[(row0 + (f >> 7)) * DI + (f & 127)];
    __syncthreads();
    const int rr = tid >> 3, jg = tid & 7;
    float acc[5];
#pragma unroll
    for (int q = 0; q < 5; q++) acc[q] = 0.f;
#pragma unroll 4
    for (int k = 0; k < 128; k++) {
        const float xv = xs[rr][k];
#pragma unroll
        for (int q = 0; q < 5; q++) {
            const int j = jg + q * 8;
            if (j < 36) acc[q] += xv * Wxs[j][k];
        }
    }
#pragma unroll
    for (int q = 0; q < 5; q++) {
        const int j = jg + q * 8;
        if (j < 36) dbl[rr][j] = acc[q];
    }
    __syncthreads();
    {
        const int d = tid;
        const float w0 = Wdts[d * 4], w1 = Wdts[d * 4 + 1];
        const float w2 = Wdts[d * 4 + 2], w3 = Wdts[d * 4 + 3];
        const float bb = bdts[d];
#pragma unroll
        for (int q = 0; q < 16; q++) {
            float v = bb + dbl[q][0] * w0 + dbl[q][1] * w1 + dbl[q][2] * w2 + dbl[q][3] * w3;
            g_dt[(row0 + q) * DI + d] = fsoftplus(v);
        }
    }
    for (int f = tid; f < 16 * 32; f += 128) {
        const int q = f >> 5, c = f & 31;
        const float v = dbl[q][4 + c];
        if (c < 16) g_B[(row0 + q) * NS + c] = v;
        else        g_C[(row0 + q) * NS + (c - 16)] = v;
    }
}

// ========== K5: selective scan; exp(dt*A_n) = p^(n+1) fast path ==========
template <bool FAST>
__device__ __forceinline__ float scan_body(int b, int d, int half, int tid,
                                           const float* c2, float dsk, float* sBC) {
    float h[8];
#pragma unroll
    for (int n = 0; n < 8; n++) h[n] = 0.f;
    float ys = 0.f;
    for (int tc = 0; tc < 4; tc++) {
        __syncthreads();
#pragma unroll
        for (int it = 0; it < 16; it++) {
            const int f = tid + it * 128;
            const int tt = f >> 5, c = f & 31;
            const int i = b * TT + tc * 64 + tt;
            sBC[f] = (c < 16) ? g_B[i * NS + c] : g_C[i * NS + (c - 16)];
        }
        __syncthreads();
        for (int t = 0; t < 64; t++) {
            const int base = (b * TT + tc * 64 + t) * DI + d;
            const float dt = g_dt[base];
            const float xc = g_xconv[base];
            const float gg = g_gates[base];
            const float dtx = dt * xc;
            float e[8];
            if (FAST) {
                const float p = fexp2(-dt * LOG2E);
                if (half == 0) {
                    e[0] = p;
#pragma unroll
                    for (int n = 1; n < 8; n++) e[n] = e[n - 1] * p;
                } else {
                    const float p2 = p * p, p4 = p2 * p2, p8 = p4 * p4;
                    e[0] = p8 * p;
#pragma unroll
                    for (int n = 1; n < 8; n++) e[n] = e[n - 1] * p;
                }
            } else {
#pragma unroll
                for (int n = 0; n < 8; n++) e[n] = fexp2(dt * c2[n]);
            }
            const float* bc = &sBC[t * 32 + half * 8];
            float yp = 0.f;
#pragma unroll
            for (int n = 0; n < 8; n++) {
                h[n] = e[n] * h[n] + dtx * bc[n];
                yp += h[n] * bc[16 + n];
            }
            const float yo = yp + __shfl_xor_sync(0xffffffffu, yp, 1);
            ys += (yo + dsk * xc) * gg;
        }
    }
    return ys;
}

__global__ void k5_scan(const float* __restrict__ A_log, const float* __restrict__ Dskip) {
    __shared__ float sBC[64 * 32];
    const int tid = threadIdx.x;
    const int b = blockIdx.x >> 1, dbase = (blockIdx.x & 1) * 64;
    const int half = tid & 1;
    const int d = dbase + (tid >> 1);

    float c2[8];
    bool fast = true;
#pragma unroll
    for (int n = 0; n < 8; n++) {
        const float a = fexp(A_log[d * NS + half * 8 + n]);
        const float tgt = (float)(half * 8 + n + 1);
        if (fabsf(a - tgt) > 1e-3f * tgt) fast = false;
        c2[n] = -a * LOG2E;
    }
    fast = __all_sync(0xffffffffu, fast);
    const float dsk = Dskip[d];
    float ys = fast ? scan_body<true>(b, d, half, tid, c2, dsk, sBC)
                    : scan_body<false>(b, d, half, tid, c2, dsk, sBC);
    if (half == 0) g_ybar[b * DI + d] = ys * (1.f / 256.f);
}

// ========== K6: heads ==========
__global__ void k6_heads(const float* __restrict__ Wout,
                         const float* __restrict__ Wfc, const float* __restrict__ bfc,
                         const float* __restrict__ Wmu, const float* __restrict__ bmu,
                         const float* __restrict__ Wsig, const float* __restrict__ bsig,
                         float* __restrict__ out) {
    __shared__ float yb[DI], ev[DM], xsm[DI];
    const int b = blockIdx.x, tid = threadIdx.x;
    yb[tid] = g_ybar[b * DI + tid];
    __syncthreads();
    if (tid < DM) {
        float s = 0.f;
#pragma unroll 4
        for (int dd = 0; dd < DI; dd++) s += yb[dd] * Wout[tid * DI + dd];
        ev[tid] = s;
    }
    __syncthreads();
    {
        float v = bfc[tid];
#pragma unroll 4
        for (int m = 0; m < DM; m++) v += ev[m] * Wfc[tid * DM + m];
        const float t = tanhf(v);
        const float x = (t > 0.f) ? t : expm1f(t);
        xsm[tid] = x;
        out[b * DI + tid] = x;
    }
    __syncthreads();
    for (int o = tid; o < 256; o += 128) {
        float sm = bmu[o], sg = bsig[o];
#pragma unroll 4
        for (int l = 0; l < DI; l++) {
            const float xv = xsm[l];
            sm += xv * Wmu[o * DI + l];
            sg += xv * Wsig[o * DI + l];
        }
        out[NB * DI + b * 256 + o] = sm;
        const float e2 = (sg > 0.f) ? sg : expm1f(sg);
        out[NB * DI + NB * 256 + b * 256 + o] = e2 + 1.f + 1e-14f;
    }
}

extern "C" void kernel_launch(void* const* d_in, const int* in_sizes, int n_in,
                              void* d_out, int out_size) {
    const float* input  = (const float*)d_in[0];
    const float* W_enc  = (const float*)d_in[1];
    const float* b_enc  = (const float*)d_in[2];
    const float* W_in   = (const float*)d_in[3];
    const float* conv_w = (const float*)d_in[4];
    const float* conv_b = (const float*)d_in[5];
    const float* W_x    = (const float*)d_in[6];
    const float* W_dt   = (const float*)d_in[7];
    const float* b_dt   = (const float*)d_in[8];
    const float* A_log  = (const float*)d_in[9];
    const float* D_skip = (const float*)d_in[10];
    const float* W_out  = (const float*)d_in[11];
    const float* W_fc   = (const float*)d_in[12];
    const float* b_fc   = (const float*)d_in[13];
    const float* W_mu   = (const float*)d_in[14];
    const float* b_mu   = (const float*)d_in[15];
    const float* W_sig  = (const float*)d_in[16];
    const float* b_sig  = (const float*)d_in[17];
    float* out = (float*)d_out;

    k0_brepack<<<(DM * DINP) / 256, 256>>>(W_enc);
    k1_gemm<<<BT / 64, 128>>>(input, b_enc);
    k2_inproj<<<BT / 8, 256>>>(W_in);
    k3_conv<<<(BT * DI) / 256, 256>>>(conv_w, conv_b);
    k4_xproj<<<BT / 16, 128>>>(W_x, W_dt, b_dt);
    k5_scan<<<NB * 2, 128>>>(A_log, D_skip);
    k6_heads<<<NB, 128>>>(W_out, W_fc, b_fc, W_mu, b_mu, W_sig, b_sig, out);
}

// round 7
// speedup vs baseline: 1.4218x; 1.2002x over previous
#include <cuda_runtime.h>
#include <cstdint>

#define BT     16384
#define TT     256
#define NB     64
#define DIN    5881
#define DM     64
#define DI     128
#define NS     16
#define NIT    184        // ceil(5881/32)
#define LOG2E  1.4426950408889634f

typedef unsigned short ushortT;
typedef unsigned int uintT;

__device__ float g_z[BT * DM];
__device__ float g_x[BT * DI];
__device__ float g_gates[BT * DI];
__device__ float g_xconv[BT * DI];
__device__ float g_dt[BT * DI];
__device__ float g_B[BT * NS];
__device__ float g_C[BT * NS];
__device__ float g_ybar[NB * DI];
// W_enc pre-tiled per k-iteration: [it][row<64][16 uints (= 32 bf16)], hi and lo planes
__device__ __align__(16) uintT g_Bpkh[NIT * 64 * 16];
__device__ __align__(16) uintT g_Bpkl[NIT * 64 * 16];

__device__ __forceinline__ float fexp2(float x) {
    float y; asm("ex2.approx.f32 %0, %1;" : "=f"(y) : "f"(x)); return y;
}
__device__ __forceinline__ float fexp(float x) { return fexp2(x * LOG2E); }
__device__ __forceinline__ float flog2(float x) {
    float y; asm("lg2.approx.f32 %0, %1;" : "=f"(y) : "f"(x)); return y;
}
__device__ __forceinline__ float fsilu(float x) { return __fdividef(x, 1.f + fexp(-x)); }
__device__ __forceinline__ float fsoftplus(float x) {
    return fmaxf(x, 0.f) + 0.6931471805599453f * flog2(1.f + fexp(-fabsf(x)));
}
__device__ __forceinline__ uintT cvt2(float lo, float hi) {
    uintT r; asm("cvt.rn.bf16x2.f32 %0, %1, %2;" : "=r"(r) : "f"(hi), "f"(lo)); return r;
}
__device__ __forceinline__ void ldsm4(uintT* r, const ushortT* p) {
    uintT a = (uintT)__cvta_generic_to_shared(p);
    asm volatile("ldmatrix.sync.aligned.m8n8.x4.shared.b16 {%0,%1,%2,%3}, [%4];"
        : "=r"(r[0]), "=r"(r[1]), "=r"(r[2]), "=r"(r[3]) : "r"(a));
}
__device__ __forceinline__ void mma16816(float* c, const uintT* a, uintT b0, uintT b1) {
    asm volatile("mma.sync.aligned.m16n8k16.row.col.f32.bf16.bf16.f32 "
        "{%0,%1,%2,%3}, {%4,%5,%6,%7}, {%8,%9}, {%0,%1,%2,%3};"
        : "+f"(c[0]), "+f"(c[1]), "+f"(c[2]), "+f"(c[3])
        : "r"(a[0]), "r"(a[1]), "r"(a[2]), "r"(a[3]), "r"(b0), "r"(b1));
}

// ========== K0: repack W_enc -> per-iter bf16 hi/lo tiles ==========
// entry gid -> (it, row, c): k = it*32 + 2c, pair (k, k+1)
__global__ void k0_brepack(const float* __restrict__ W) {
    const int gid = blockIdx.x * 256 + threadIdx.x;    // NIT*64*16 = 188416
    if (gid >= NIT * 64 * 16) return;
    const int c   = gid & 15;
    const int row = (gid >> 4) & 63;
    const int it  = gid >> 10;
    const int k   = it * 32 + c * 2;
    const float v0 = (k < DIN)     ? W[row * DIN + k]     : 0.f;
    const float v1 = (k + 1 < DIN) ? W[row * DIN + k + 1] : 0.f;
    const uintT xh = cvt2(v0, v1);
    const float h0 = __uint_as_float(xh << 16);
    const float h1 = __uint_as_float(xh & 0xffff0000u);
    g_Bpkh[gid] = xh;
    g_Bpkl[gid] = cvt2(v0 - h0, v1 - h1);
}

// ========== K1: encoder GEMM via bf16x3 tensor MMA ==========
// C[16384,64] = A[16384,5881] @ W^T. BM=128, BN=64, BK=32, 256 threads (8 warps).
// Coalesced A loads: round i -> row = i*8 + warp, k = lane.
__global__ void __launch_bounds__(256) k1_gemm(const float* __restrict__ A,
                                               const float* __restrict__ be) {
    __shared__ __align__(16) ushortT sAh[128 * 40], sAl[128 * 40];
    __shared__ __align__(16) ushortT sBh[64 * 40],  sBl[64 * 40];
    const int tid  = threadIdx.x;
    const int lane = tid & 31, warp = tid >> 5;   // warp 0..7
    const int row0 = blockIdx.x * 128;

    float w[16];
    uint4 bqh, bql;

    auto loadT = [&](int it) {
        const int kb = it * 32;
        if (it < NIT - 1) {
#pragma unroll
            for (int i = 0; i < 16; i++)
                w[i] = A[(row0 + i * 8 + warp) * DIN + kb + lane];
        } else {
            const bool in = (kb + lane < DIN);
#pragma unroll
            for (int i = 0; i < 16; i++)
                w[i] = in ? A[(row0 + i * 8 + warp) * DIN + kb + lane] : 0.f;
        }
        bqh = ((const uint4*)g_Bpkh)[it * 256 + tid];
        bql = ((const uint4*)g_Bpkl)[it * 256 + tid];
    };
    auto stage = [&]() {
#pragma unroll
        for (int i = 0; i < 16; i++) {
            const int row = i * 8 + warp;
            const float v = w[i];
            const uintT xh = cvt2(v, 0.f);
            const float hf = __uint_as_float(xh << 16);
            const uintT xl = cvt2(v - hf, 0.f);
            sAh[row * 40 + lane] = (ushortT)xh;
            sAl[row * 40 + lane] = (ushortT)xl;
        }
        const int br = tid >> 2;            // B row 0..63
        const int bc = (tid & 3) * 16;      // byte offset within row (0,16,32,48)
        *(uint4*)((char*)sBh + br * 80 + bc) = bqh;
        *(uint4*)((char*)sBl + br * 80 + bc) = bql;
    };

    float acc[8][4];
#pragma unroll
    for (int j = 0; j < 8; j++)
#pragma unroll
        for (int q = 0; q < 4; q++) acc[j][q] = 0.f;

    const int wr0 = warp * 16;
    loadT(0);
    for (int it = 0; it < NIT; it++) {
        stage();
        __syncthreads();
        if (it < NIT - 1) loadT(it + 1);
#pragma unroll
        for (int s = 0; s < 2; s++) {
            uintT ah[4], al[4], bh[4], bl[4];
            const int aoff = (wr0 + (lane & 15)) * 40 + 16 * s + ((lane >> 4) << 3);
            ldsm4(ah, sAh + aoff);
            ldsm4(al, sAl + aoff);
#pragma unroll
            for (int p = 0; p < 4; p++) {
                const int boff = (16 * p + ((lane >> 4) << 3) + (lane & 7)) * 40
                               + 16 * s + (lane & 8);
                ldsm4(bh, sBh + boff);
                ldsm4(bl, sBl + boff);
                mma16816(acc[2 * p],     ah, bh[0], bh[1]);
                mma16816(acc[2 * p],     ah, bl[0], bl[1]);
                mma16816(acc[2 * p],     al, bh[0], bh[1]);
                mma16816(acc[2 * p + 1], ah, bh[2], bh[3]);
                mma16816(acc[2 * p + 1], ah, bl[2], bl[3]);
                mma16816(acc[2 * p + 1], al, bh[2], bh[3]);
            }
        }
        __syncthreads();
    }
    const int orow = row0 + wr0 + (lane >> 2);
    const int cb = (lane & 3) * 2;
#pragma unroll
    for (int j = 0; j < 8; j++) {
        const int c = 8 * j + cb;
        const float b0 = __ldg(be + c), b1 = __ldg(be + c + 1);
        *(float2*)&g_z[orow * DM + c] = make_float2(acc[j][0] + b0, acc[j][1] + b1);
        *(float2*)&g_z[(orow + 8) * DM + c] = make_float2(acc[j][2] + b0, acc[j][3] + b1);
    }
}

// ========== K2: in-proj + silu(gate) ==========
__global__ void k2_inproj(const float* __restrict__ Win) {
    __shared__ float zs[8][64];
    const int tid = threadIdx.x, row0 = blockIdx.x * 8;
#pragma unroll
    for (int it = 0; it < 2; it++) {
        const int f = tid + it * 256;
        zs[f >> 6][f & 63] = g_z[(row0 + (f >> 6)) * DM + (f & 63)];
    }
    __syncthreads();
    const int c = tid;
    float acc[8];
#pragma unroll
    for (int rr = 0; rr < 8; rr++) acc[rr] = 0.f;
#pragma unroll 8
    for (int k = 0; k < 64; k++) {
        const float wv = Win[c * 64 + k];
#pragma unroll
        for (int rr = 0; rr < 8; rr++) acc[rr] += zs[rr][k] * wv;
    }
#pragma unroll
    for (int rr = 0; rr < 8; rr++) {
        const int i = row0 + rr;
        if (c < DI) g_x[i * DI + c] = acc[rr];
        else        g_gates[i * DI + (c - DI)] = fsilu(acc[rr]);
    }
}

// ========== K3: causal depthwise conv(4) + silu ==========
__global__ void k3_conv(const float* __restrict__ cw, const float* __restrict__ cb) {
    const int gid = blockIdx.x * 256 + threadIdx.x;
    const int d = gid & 127, i = gid >> 7, t = i & 255;
    float s = cb[d];
#pragma unroll
    for (int k = 0; k < 4; k++) {
        const int tk = t + k - 3;
        if (tk >= 0) s += g_x[(i - t + tk) * DI + d] * cw[d * 4 + k];
    }
    g_xconv[gid] = fsilu(s);
}

// ========== K4: x-proj + dt path + B/C ==========
__global__ void k4_xproj(const float* __restrict__ Wx, const float* __restrict__ Wdt,
                         const float* __restrict__ bdt) {
    __shared__ float xs[16][129], Wxs[36][132], dbl[16][40], Wdts[DI * 4], bdts[DI];
    const int tid = threadIdx.x, row0 = blockIdx.x * 16;
    for (int f = tid; f < 36 * 128; f += 128) Wxs[f >> 7][f & 127] = Wx[f];
    for (int f = tid; f < DI * 4; f += 128) Wdts[f] = Wdt[f];
    if (tid < DI) bdts[tid] = bdt[tid];
    for (int f = tid; f < 16 * 128; f += 128)
        xs[f >> 7][f & 127] = g_xconv[(row0 + (f >> 7)) * DI + (f & 127)];
    __syncthreads();
    const int rr = tid >> 3, jg = tid & 7;
    float acc[5];
#pragma unroll
    for (int q = 0; q < 5; q++) acc[q] = 0.f;
#pragma unroll 4
    for (int k = 0; k < 128; k++) {
        const float xv = xs[rr][k];
#pragma unroll
        for (int q = 0; q < 5; q++) {
            const int j = jg + q * 8;
            if (j < 36) acc[q] += xv * Wxs[j][k];
        }
    }
#pragma unroll
    for (int q = 0; q < 5; q++) {
        const int j = jg + q * 8;
        if (j < 36) dbl[rr][j] = acc[q];
    }
    __syncthreads();
    {
        const int d = tid;
        const float w0 = Wdts[d * 4], w1 = Wdts[d * 4 + 1];
        const float w2 = Wdts[d * 4 + 2], w3 = Wdts[d * 4 + 3];
        const float bb = bdts[d];
#pragma unroll
        for (int q = 0; q < 16; q++) {
            float v = bb + dbl[q][0] * w0 + dbl[q][1] * w1 + dbl[q][2] * w2 + dbl[q][3] * w3;
            g_dt[(row0 + q) * DI + d] = fsoftplus(v);
        }
    }
    for (int f = tid; f < 16 * 32; f += 128) {
        const int q = f >> 5, c = f & 31;
        const float v = dbl[q][4 + c];
        if (c < 16) g_B[(row0 + q) * NS + c] = v;
        else        g_C[(row0 + q) * NS + (c - 16)] = v;
    }
}

// ========== K5: selective scan; exp(dt*A_n) = p^(n+1) fast path ==========
template <bool FAST>
__device__ __forceinline__ float scan_body(int b, int d, int half, int tid,
                                           const float* c2, float dsk, float* sBC) {
    float h[8];
#pragma unroll
    for (int n = 0; n < 8; n++) h[n] = 0.f;
    float ys = 0.f;
    for (int tc = 0; tc < 4; tc++) {
        __syncthreads();
#pragma unroll
        for (int it = 0; it < 16; it++) {
            const int f = tid + it * 128;
            const int tt = f >> 5, c = f & 31;
            const int i = b * TT + tc * 64 + tt;
            sBC[f] = (c < 16) ? g_B[i * NS + c] : g_C[i * NS + (c - 16)];
        }
        __syncthreads();
        for (int t = 0; t < 64; t++) {
            const int base = (b * TT + tc * 64 + t) * DI + d;
            const float dt = g_dt[base];
            const float xc = g_xconv[base];
            const float gg = g_gates[base];
            const float dtx = dt * xc;
            float e[8];
            if (FAST) {
                const float p = fexp2(-dt * LOG2E);
                if (half == 0) {
                    e[0] = p;
#pragma unroll
                    for (int n = 1; n < 8; n++) e[n] = e[n - 1] * p;
                } else {
                    const float p2 = p * p, p4 = p2 * p2, p8 = p4 * p4;
                    e[0] = p8 * p;
#pragma unroll
                    for (int n = 1; n < 8; n++) e[n] = e[n - 1] * p;
                }
            } else {
#pragma unroll
                for (int n = 0; n < 8; n++) e[n] = fexp2(dt * c2[n]);
            }
            const float* bc = &sBC[t * 32 + half * 8];
            float yp = 0.f;
#pragma unroll
            for (int n = 0; n < 8; n++) {
                h[n] = e[n] * h[n] + dtx * bc[n];
                yp += h[n] * bc[16 + n];
            }
            const float yo = yp + __shfl_xor_sync(0xffffffffu, yp, 1);
            ys += (yo + dsk * xc) * gg;
        }
    }
    return ys;
}

__global__ void k5_scan(const float* __restrict__ A_log, const float* __restrict__ Dskip) {
    __shared__ float sBC[64 * 32];
    const int tid = threadIdx.x;
    const int b = blockIdx.x >> 1, dbase = (blockIdx.x & 1) * 64;
    const int half = tid & 1;
    const int d = dbase + (tid >> 1);

    float c2[8];
    bool fast = true;
#pragma unroll
    for (int n = 0; n < 8; n++) {
        const float a = fexp(A_log[d * NS + half * 8 + n]);
        const float tgt = (float)(half * 8 + n + 1);
        if (fabsf(a - tgt) > 1e-3f * tgt) fast = false;
        c2[n] = -a * LOG2E;
    }
    fast = __all_sync(0xffffffffu, fast);
    const float dsk = Dskip[d];
    float ys = fast ? scan_body<true>(b, d, half, tid, c2, dsk, sBC)
                    : scan_body<false>(b, d, half, tid, c2, dsk, sBC);
    if (half == 0) g_ybar[b * DI + d] = ys * (1.f / 256.f);
}

// ========== K6: heads ==========
__global__ void k6_heads(const float* __restrict__ Wout,
                         const float* __restrict__ Wfc, const float* __restrict__ bfc,
                         const float* __restrict__ Wmu, const float* __restrict__ bmu,
                         const float* __restrict__ Wsig, const float* __restrict__ bsig,
                         float* __restrict__ out) {
    __shared__ float yb[DI], ev[DM], xsm[DI];
    const int b = blockIdx.x, tid = threadIdx.x;
    yb[tid] = g_ybar[b * DI + tid];
    __syncthreads();
    if (tid < DM) {
        float s = 0.f;
#pragma unroll 4
        for (int dd = 0; dd < DI; dd++) s += yb[dd] * Wout[tid * DI + dd];
        ev[tid] = s;
    }
    __syncthreads();
    {
        float v = bfc[tid];
#pragma unroll 4
        for (int m = 0; m < DM; m++) v += ev[m] * Wfc[tid * DM + m];
        const float t = tanhf(v);
        const float x = (t > 0.f) ? t : expm1f(t);
        xsm[tid] = x;
        out[b * DI + tid] = x;
    }
    __syncthreads();
    for (int o = tid; o < 256; o += 128) {
        float sm = bmu[o], sg = bsig[o];
#pragma unroll 4
        for (int l = 0; l < DI; l++) {
            const float xv = xsm[l];
            sm += xv * Wmu[o * DI + l];
            sg += xv * Wsig[o * DI + l];
        }
        out[NB * DI + b * 256 + o] = sm;
        const float e2 = (sg > 0.f) ? sg : expm1f(sg);
        out[NB * DI + NB * 256 + b * 256 + o] = e2 + 1.f + 1e-14f;
    }
}

extern "C" void kernel_launch(void* const* d_in, const int* in_sizes, int n_in,
                              void* d_out, int out_size) {
    const float* input  = (const float*)d_in[0];
    const float* W_enc  = (const float*)d_in[1];
    const float* b_enc  = (const float*)d_in[2];
    const float* W_in   = (const float*)d_in[3];
    const float* conv_w = (const float*)d_in[4];
    const float* conv_b = (const float*)d_in[5];
    const float* W_x    = (const float*)d_in[6];
    const float* W_dt   = (const float*)d_in[7];
    const float* b_dt   = (const float*)d_in[8];
    const float* A_log  = (const float*)d_in[9];
    const float* D_skip = (const float*)d_in[10];
    const float* W_out  = (const float*)d_in[11];
    const float* W_fc   = (const float*)d_in[12];
    const float* b_fc   = (const float*)d_in[13];
    const float* W_mu   = (const float*)d_in[14];
    const float* b_mu   = (const float*)d_in[15];
    const float* W_sig  = (const float*)d_in[16];
    const float* b_sig  = (const float*)d_in[17];
    float* out = (float*)d_out;

    k0_brepack<<<(NIT * 64 * 16 + 255) / 256, 256>>>(W_enc);
    k1_gemm<<<BT / 128, 256>>>(input, b_enc);
    k2_inproj<<<BT / 8, 256>>>(W_in);
    k3_conv<<<(BT * DI) / 256, 256>>>(conv_w, conv_b);
    k4_xproj<<<BT / 16, 128>>>(W_x, W_dt, b_dt);
    k5_scan<<<NB * 2, 128>>>(A_log, D_skip);
    k6_heads<<<NB, 128>>>(W_out, W_fc, b_fc, W_mu, b_mu, W_sig, b_sig, out);
}

// round 10
// speedup vs baseline: 1.8294x; 1.2867x over previous
#include <cuda_runtime.h>
#include <cstdint>

#define BT     16384
#define TT     256
#define NB     64
#define DIN    5881
#define DM     64
#define DI     128
#define NS     16
#define NIT    184        // ceil(5881/32)
#define LOG2E  1.4426950408889634f

typedef unsigned short ushortT;
typedef unsigned int uintT;

__device__ float g_z[BT * DM];
__device__ float g_x[BT * DI];
__device__ float g_gates[BT * DI];
__device__ float g_xconv[BT * DI];
__device__ float g_dt[BT * DI];
__device__ float g_B[BT * NS];
__device__ float g_C[BT * NS];
__device__ float g_ybar[NB * DI];
// W_enc pre-tiled per k-iteration: [it][row<64][16 uints (= 32 bf16)], hi and lo planes
__device__ __align__(16) uintT g_Bpkh[NIT * 64 * 16];
__device__ __align__(16) uintT g_Bpkl[NIT * 64 * 16];
// W_in transposed: [k<64][c<256]
__device__ float g_WinT[DM * 2 * DI];

__device__ __forceinline__ float fexp2(float x) {
    float y; asm("ex2.approx.f32 %0, %1;" : "=f"(y) : "f"(x)); return y;
}
__device__ __forceinline__ float fexp(float x) { return fexp2(x * LOG2E); }
__device__ __forceinline__ float flog2(float x) {
    float y; asm("lg2.approx.f32 %0, %1;" : "=f"(y) : "f"(x)); return y;
}
__device__ __forceinline__ float fsilu(float x) { return __fdividef(x, 1.f + fexp(-x)); }
__device__ __forceinline__ float fsoftplus(float x) {
    return fmaxf(x, 0.f) + 0.6931471805599453f * flog2(1.f + fexp(-fabsf(x)));
}
__device__ __forceinline__ uintT cvt2(float lo, float hi) {
    uintT r; asm("cvt.rn.bf16x2.f32 %0, %1, %2;" : "=r"(r) : "f"(hi), "f"(lo)); return r;
}
__device__ __forceinline__ void ldsm4(uintT* r, const ushortT* p) {
    uintT a = (uintT)__cvta_generic_to_shared(p);
    asm volatile("ldmatrix.sync.aligned.m8n8.x4.shared.b16 {%0,%1,%2,%3}, [%4];"
        : "=r"(r[0]), "=r"(r[1]), "=r"(r[2]), "=r"(r[3]) : "r"(a));
}
__device__ __forceinline__ void mma16816(float* c, const uintT* a, uintT b0, uintT b1) {
    asm volatile("mma.sync.aligned.m16n8k16.row.col.f32.bf16.bf16.f32 "
        "{%0,%1,%2,%3}, {%4,%5,%6,%7}, {%8,%9}, {%0,%1,%2,%3};"
        : "+f"(c[0]), "+f"(c[1]), "+f"(c[2]), "+f"(c[3])
        : "r"(a[0]), "r"(a[1]), "r"(a[2]), "r"(a[3]), "r"(b0), "r"(b1));
}

// ========== K0: repack W_enc -> per-iter bf16 hi/lo tiles ==========
__global__ void k0_brepack(const float* __restrict__ W) {
    const int gid = blockIdx.x * 256 + threadIdx.x;    // NIT*64*16 = 188416
    if (gid >= NIT * 64 * 16) return;
    const int c   = gid & 15;
    const int row = (gid >> 4) & 63;
    const int it  = gid >> 10;
    const int k   = it * 32 + c * 2;
    const float v0 = (k < DIN)     ? W[row * DIN + k]     : 0.f;
    const float v1 = (k + 1 < DIN) ? W[row * DIN + k + 1] : 0.f;
    const uintT xh = cvt2(v0, v1);
    const float h0 = __uint_as_float(xh << 16);
    const float h1 = __uint_as_float(xh & 0xffff0000u);
    g_Bpkh[gid] = xh;
    g_Bpkl[gid] = cvt2(v0 - h0, v1 - h1);
}

// ========== K0b: transpose W_in -> [k][c] for coalesced k2 ==========
__global__ void k0b_wtr(const float* __restrict__ Win) {
    const int gid = blockIdx.x * 256 + threadIdx.x;    // 256*64 = 16384
    const int c = gid >> 6, k = gid & 63;
    g_WinT[k * 2 * DI + c] = Win[gid];
}

// ========== K1: encoder GEMM, bf16x3 MMA, k-half-split warps ==========
// C[16384,64] = A[16384,5881] @ W^T. BM=64, BN=64, BK=32, 256 thr (8 warps).
// Warp w: rows (w&3)*16..+16, k-half s = w>>2. Partials merged via smem epilogue.
__global__ void __launch_bounds__(256) k1_gemm(const float* __restrict__ A,
                                               const float* __restrict__ be) {
    __shared__ __align__(16) char smem_raw[20480];
    ushortT* sAh = (ushortT*)smem_raw;            // 64*40
    ushortT* sAl = (ushortT*)(smem_raw + 5120);
    ushortT* sBh = (ushortT*)(smem_raw + 10240);
    ushortT* sBl = (ushortT*)(smem_raw + 15360);

    const int tid  = threadIdx.x;
    const int lane = tid & 31, warp = tid >> 5;   // 0..7
    const int row0 = blockIdx.x * 64;
    const int s    = warp >> 2;                   // k-half
    const int mrow = (warp & 3) * 16;

    float w8[8];
    uint4 bqh, bql;

    auto loadR = [&](int it) {
        const int kb = it * 32;
        if (it < NIT - 1) {
#pragma unroll
            for (int i = 0; i < 8; i++)
                w8[i] = A[(size_t)(row0 + i * 8 + warp) * DIN + kb + lane];
        } else {
            const bool in = (kb + lane) < DIN;
#pragma unroll
            for (int i = 0; i < 8; i++)
                w8[i] = in ? A[(size_t)(row0 + i * 8 + warp) * DIN + kb + lane] : 0.f;
        }
        bqh = ((const uint4*)g_Bpkh)[it * 256 + tid];
        bql = ((const uint4*)g_Bpkl)[it * 256 + tid];
    };
    auto stage = [&]() {
#pragma unroll
        for (int i = 0; i < 8; i++) {
            const float v = w8[i];
            const uintT xh = cvt2(v, 0.f);
            const float hf = __uint_as_float(xh << 16);
            const uintT xl = cvt2(v - hf, 0.f);
            sAh[(i * 8 + warp) * 40 + lane] = (ushortT)xh;
            sAl[(i * 8 + warp) * 40 + lane] = (ushortT)xl;
        }
        const int br = tid >> 2, bc = (tid & 3) * 16;
        *(uint4*)((char*)sBh + br * 80 + bc) = bqh;
        *(uint4*)((char*)sBl + br * 80 + bc) = bql;
    };

    float acc[8][4];
#pragma unroll
    for (int j = 0; j < 8; j++)
#pragma unroll
        for (int q = 0; q < 4; q++) acc[j][q] = 0.f;

    loadR(0);
    for (int it = 0; it < NIT; it++) {
        stage();
        __syncthreads();
        if (it < NIT - 1) loadR(it + 1);
        uintT ah[4], al[4], bh[4], bl[4];
        const int aoff = (mrow + (lane & 15)) * 40 + 16 * s + ((lane >> 4) << 3);
        ldsm4(ah, sAh + aoff);
        ldsm4(al, sAl + aoff);
#pragma unroll
        for (int p = 0; p < 4; p++) {
            const int boff = (16 * p + ((lane >> 4) << 3) + (lane & 7)) * 40
                           + 16 * s + (lane & 8);
            ldsm4(bh, sBh + boff);
            ldsm4(bl, sBl + boff);
            mma16816(acc[2 * p],     ah, bh[0], bh[1]);
            mma16816(acc[2 * p],     ah, bl[0], bl[1]);
            mma16816(acc[2 * p],     al, bh[0], bh[1]);
            mma16816(acc[2 * p + 1], ah, bh[2], bh[3]);
            mma16816(acc[2 * p + 1], ah, bl[2], bl[3]);
            mma16816(acc[2 * p + 1], al, bh[2], bh[3]);
        }
        __syncthreads();
    }

    // epilogue: merge s=1 partials into s=0 warps via smem scratch (pitch 66)
    float* scr = (float*)smem_raw;
    const int r0 = mrow + (lane >> 2);
    const int cbase = (lane & 3) * 2;
    if (warp >= 4) {
#pragma unroll
        for (int j = 0; j < 8; j++) {
            const int c = 8 * j + cbase;
            *(float2*)&scr[r0 * 66 + c] = make_float2(acc[j][0], acc[j][1]);
            *(float2*)&scr[(r0 + 8) * 66 + c] = make_float2(acc[j][2], acc[j][3]);
        }
    }
    __syncthreads();
    if (warp < 4) {
#pragma unroll
        for (int j = 0; j < 8; j++) {
            const int c = 8 * j + cbase;
            const float2 p0 = *(const float2*)&scr[r0 * 66 + c];
            const float2 p1 = *(const float2*)&scr[(r0 + 8) * 66 + c];
            const float b0 = __ldg(be + c), b1 = __ldg(be + c + 1);
            *(float2*)&g_z[(row0 + r0) * DM + c] =
                make_float2(acc[j][0] + p0.x + b0, acc[j][1] + p0.y + b1);
            *(float2*)&g_z[(row0 + r0 + 8) * DM + c] =
                make_float2(acc[j][2] + p1.x + b0, acc[j][3] + p1.y + b1);
        }
    }
}

// ========== K2: in-proj + silu(gate), coalesced via WinT ==========
__global__ void k2_inproj() {
    __shared__ float zs[8][64];
    const int tid = threadIdx.x, row0 = blockIdx.x * 8;
#pragma unroll
    for (int it = 0; it < 2; it++) {
        const int f = tid + it * 256;
        zs[f >> 6][f & 63] = g_z[(row0 + (f >> 6)) * DM + (f & 63)];
    }
    __syncthreads();
    const int c = tid;
    float acc[8];
#pragma unroll
    for (int rr = 0; rr < 8; rr++) acc[rr] = 0.f;
#pragma unroll 8
    for (int k = 0; k < 64; k++) {
        const float wv = g_WinT[k * 2 * DI + c];
#pragma unroll
        for (int rr = 0; rr < 8; rr++) acc[rr] += zs[rr][k] * wv;
    }
#pragma unroll
    for (int rr = 0; rr < 8; rr++) {
        const int i = row0 + rr;
        if (c < DI) g_x[i * DI + c] = acc[rr];
        else        g_gates[i * DI + (c - DI)] = fsilu(acc[rr]);
    }
}

// ========== K3: causal depthwise conv(4) + silu ==========
__global__ void k3_conv(const float* __restrict__ cw, const float* __restrict__ cb) {
    const int gid = blockIdx.x * 256 + threadIdx.x;
    const int d = gid & 127, i = gid >> 7, t = i & 255;
    float s = cb[d];
#pragma unroll
    for (int k = 0; k < 4; k++) {
        const int tk = t + k - 3;
        if (tk >= 0) s += g_x[(i - t + tk) * DI + d] * cw[d * 4 + k];
    }
    g_xconv[gid] = fsilu(s);
}

// ========== K4: x-proj + dt path + B/C ==========
__global__ void k4_xproj(const float* __restrict__ Wx, const float* __restrict__ Wdt,
                         const float* __restrict__ bdt) {
    __shared__ float xs[16][129], Wxs[36][132], dbl[16][40], Wdts[DI * 4], bdts[DI];
    const int tid = threadIdx.x, row0 = blockIdx.x * 16;
    for (int f = tid; f < 36 * 128; f += 128) Wxs[f >> 7][f & 127] = Wx[f];
    for (int f = tid; f < DI * 4; f += 128) Wdts[f] = Wdt[f];
    if (tid < DI) bdts[tid] = bdt[tid];
    for (int f = tid; f < 16 * 128; f += 128)
        xs[f >> 7][f & 127] = g_xconv[(row0 + (f >> 7)) * DI + (f & 127)];
    __syncthreads();
    const int rr = tid >> 3, jg = tid & 7;
    float acc[5];
#pragma unroll
    for (int q = 0; q < 5; q++) acc[q] = 0.f;
#pragma unroll 4
    for (int k = 0; k < 128; k++) {
        const float xv = xs[rr][k];
#pragma unroll
        for (int q = 0; q < 5; q++) {
            const int j = jg + q * 8;
            if (j < 36) acc[q] += xv * Wxs[j][k];
        }
    }
#pragma unroll
    for (int q = 0; q < 5; q++) {
        const int j = jg + q * 8;
        if (j < 36) dbl[rr][j] = acc[q];
    }
    __syncthreads();
    {
        const int d = tid;
        const float w0 = Wdts[d * 4], w1 = Wdts[d * 4 + 1];
        const float w2 = Wdts[d * 4 + 2], w3 = Wdts[d * 4 + 3];
        const float bb = bdts[d];
#pragma unroll
        for (int q = 0; q < 16; q++) {
            float v = bb + dbl[q][0] * w0 + dbl[q][1] * w1 + dbl[q][2] * w2 + dbl[q][3] * w3;
            g_dt[(row0 + q) * DI + d] = fsoftplus(v);
        }
    }
    for (int f = tid; f < 16 * 32; f += 128) {
        const int q = f >> 5, c = f & 31;
        const float v = dbl[q][4 + c];
        if (c < 16) g_B[(row0 + q) * NS + c] = v;
        else        g_C[(row0 + q) * NS + (c - 16)] = v;
    }
}

// ========== K5: selective scan; exp(dt*A_n) = p^(n+1) fast path ==========
template <bool FAST>
__device__ __forceinline__ float scan_body(int b, int d, int half, int tid,
                                           const float* c2, float dsk, float* sBC) {
    float h[8];
#pragma unroll
    for (int n = 0; n < 8; n++) h[n] = 0.f;
    float ys = 0.f;
    for (int tc = 0; tc < 4; tc++) {
        __syncthreads();
#pragma unroll
        for (int it = 0; it < 16; it++) {
            const int f = tid + it * 128;
            const int tt = f >> 5, c = f & 31;
            const int i = b * TT + tc * 64 + tt;
            sBC[f] = (c < 16) ? g_B[i * NS + c] : g_C[i * NS + (c - 16)];
        }
        __syncthreads();
        for (int t = 0; t < 64; t++) {
            const int base = (b * TT + tc * 64 + t) * DI + d;
            const float dt = g_dt[base];
            const float xc = g_xconv[base];
            const float gg = g_gates[base];
            const float dtx = dt * xc;
            float e[8];
            if (FAST) {
                const float p = fexp2(-dt * LOG2E);
                if (half == 0) {
                    e[0] = p;
#pragma unroll
                    for (int n = 1; n < 8; n++) e[n] = e[n - 1] * p;
                } else {
                    const float p2 = p * p, p4 = p2 * p2, p8 = p4 * p4;
                    e[0] = p8 * p;
#pragma unroll
                    for (int n = 1; n < 8; n++) e[n] = e[n - 1] * p;
                }
            } else {
#pragma unroll
                for (int n = 0; n < 8; n++) e[n] = fexp2(dt * c2[n]);
            }
            const float* bc = &sBC[t * 32 + half * 8];
            float yp = 0.f;
#pragma unroll
            for (int n = 0; n < 8; n++) {
                h[n] = e[n] * h[n] + dtx * bc[n];
                yp += h[n] * bc[16 + n];
            }
            const float yo = yp + __shfl_xor_sync(0xffffffffu, yp, 1);
            ys += (yo + dsk * xc) * gg;
        }
    }
    return ys;
}

__global__ void k5_scan(const float* __restrict__ A_log, const float* __restrict__ Dskip) {
    __shared__ float sBC[64 * 32];
    const int tid = threadIdx.x;
    const int b = blockIdx.x >> 1, dbase = (blockIdx.x & 1) * 64;
    const int half = tid & 1;
    const int d = dbase + (tid >> 1);

    float c2[8];
    bool fast = true;
#pragma unroll
    for (int n = 0; n < 8; n++) {
        const float a = fexp(A_log[d * NS + half * 8 + n]);
        const float tgt = (float)(half * 8 + n + 1);
        if (fabsf(a - tgt) > 1e-3f * tgt) fast = false;
        c2[n] = -a * LOG2E;
    }
    fast = __all_sync(0xffffffffu, fast);
    const float dsk = Dskip[d];
    float ys = fast ? scan_body<true>(b, d, half, tid, c2, dsk, sBC)
                    : scan_body<false>(b, d, half, tid, c2, dsk, sBC);
    if (half == 0) g_ybar[b * DI + d] = ys * (1.f / 256.f);
}

// ========== K6: heads ==========
__global__ void k6_heads(const float* __restrict__ Wout,
                         const float* __restrict__ Wfc, const float* __restrict__ bfc,
                         const float* __restrict__ Wmu, const float* __restrict__ bmu,
                         const float* __restrict__ Wsig, const float* __restrict__ bsig,
                         float* __restrict__ out) {
    __shared__ float yb[DI], ev[DM], xsm[DI];
    const int b = blockIdx.x, tid = threadIdx.x;
    yb[tid] = g_ybar[b * DI + tid];
    __syncthreads();
    if (tid < DM) {
        float s = 0.f;
#pragma unroll 4
        for (int dd = 0; dd < DI; dd++) s += yb[dd] * Wout[tid * DI + dd];
        ev[tid] = s;
    }
    __syncthreads();
    {
        float v = bfc[tid];
#pragma unroll 4
        for (int m = 0; m < DM; m++) v += ev[m] * Wfc[tid * DM + m];
        const float t = tanhf(v);
        const float x = (t > 0.f) ? t : expm1f(t);
        xsm[tid] = x;
        out[b * DI + tid] = x;
    }
    __syncthreads();
    for (int o = tid; o < 256; o += 128) {
        float sm = bmu[o], sg = bsig[o];
#pragma unroll 4
        for (int l = 0; l < DI; l++) {
            const float xv = xsm[l];
            sm += xv * Wmu[o * DI + l];
            sg += xv * Wsig[o * DI + l];
        }
        out[NB * DI + b * 256 + o] = sm;
        const float e2 = (sg > 0.f) ? sg : expm1f(sg);
        out[NB * DI + NB * 256 + b * 256 + o] = e2 + 1.f + 1e-14f;
    }
}

extern "C" void kernel_launch(void* const* d_in, const int* in_sizes, int n_in,
                              void* d_out, int out_size) {
    const float* input  = (const float*)d_in[0];
    const float* W_enc  = (const float*)d_in[1];
    const float* b_enc  = (const float*)d_in[2];
    const float* W_in   = (const float*)d_in[3];
    const float* conv_w = (const float*)d_in[4];
    const float* conv_b = (const float*)d_in[5];
    const float* W_x    = (const float*)d_in[6];
    const float* W_dt   = (const float*)d_in[7];
    const float* b_dt   = (const float*)d_in[8];
    const float* A_log  = (const float*)d_in[9];
    const float* D_skip = (const float*)d_in[10];
    const float* W_out  = (const float*)d_in[11];
    const float* W_fc   = (const float*)d_in[12];
    const float* b_fc   = (const float*)d_in[13];
    const float* W_mu   = (const float*)d_in[14];
    const float* b_mu   = (const float*)d_in[15];
    const float* W_sig  = (const float*)d_in[16];
    const float* b_sig  = (const float*)d_in[17];
    float* out = (float*)d_out;

    k0_brepack<<<(NIT * 64 * 16 + 255) / 256, 256>>>(W_enc);
    k0b_wtr<<<(2 * DI * DM) / 256, 256>>>(W_in);
    k1_gemm<<<BT / 64, 256>>>(input, b_enc);
    k2_inproj<<<BT / 8, 256>>>();
    k3_conv<<<(BT * DI) / 256, 256>>>(conv_w, conv_b);
    k4_xproj<<<BT / 16, 128>>>(W_x, W_dt, b_dt);
    k5_scan<<<NB * 2, 128>>>(A_log, D_skip);
    k6_heads<<<NB, 128>>>(W_out, W_fc, b_fc, W_mu, b_mu, W_sig, b_sig, out);
}

// round 11
// speedup vs baseline: 1.8716x; 1.0231x over previous
#include <cuda_runtime.h>
#include <cstdint>

#define BT     16384
#define TT     256
#define NB     64
#define DIN    5881
#define DM     64
#define DI     128
#define NS     16
#define NIT    184        // ceil(5881/32)
#define LOG2E  1.4426950408889634f

typedef unsigned short ushortT;
typedef unsigned int uintT;

__device__ float g_z[BT * DM];
__device__ float g_x[BT * DI];
__device__ float g_gates[BT * DI];
__device__ float g_xconv[BT * DI];
__device__ float g_dt[BT * DI];
__device__ float g_B[BT * NS];
__device__ float g_C[BT * NS];
__device__ float g_ybar[NB * DI];
// W_enc pre-tiled per k-iteration: [it][row<64][16 uints (= 32 bf16)], hi and lo planes
__device__ __align__(16) uintT g_Bpkh[NIT * 64 * 16];
__device__ __align__(16) uintT g_Bpkl[NIT * 64 * 16];
// W_in transposed: [k<64][c<256]
__device__ float g_WinT[DM * 2 * DI];

__device__ __forceinline__ float fexp2(float x) {
    float y; asm("ex2.approx.f32 %0, %1;" : "=f"(y) : "f"(x)); return y;
}
__device__ __forceinline__ float fexp(float x) { return fexp2(x * LOG2E); }
__device__ __forceinline__ float flog2(float x) {
    float y; asm("lg2.approx.f32 %0, %1;" : "=f"(y) : "f"(x)); return y;
}
__device__ __forceinline__ float fsilu(float x) { return __fdividef(x, 1.f + fexp(-x)); }
__device__ __forceinline__ float fsoftplus(float x) {
    return fmaxf(x, 0.f) + 0.6931471805599453f * flog2(1.f + fexp(-fabsf(x)));
}
__device__ __forceinline__ uintT cvt2(float lo, float hi) {
    uintT r; asm("cvt.rn.bf16x2.f32 %0, %1, %2;" : "=r"(r) : "f"(hi), "f"(lo)); return r;
}
__device__ __forceinline__ void ldsm4(uintT* r, const ushortT* p) {
    uintT a = (uintT)__cvta_generic_to_shared(p);
    asm volatile("ldmatrix.sync.aligned.m8n8.x4.shared.b16 {%0,%1,%2,%3}, [%4];"
        : "=r"(r[0]), "=r"(r[1]), "=r"(r[2]), "=r"(r[3]) : "r"(a));
}
__device__ __forceinline__ void mma16816(float* c, const uintT* a, uintT b0, uintT b1) {
    asm volatile("mma.sync.aligned.m16n8k16.row.col.f32.bf16.bf16.f32 "
        "{%0,%1,%2,%3}, {%4,%5,%6,%7}, {%8,%9}, {%0,%1,%2,%3};"
        : "+f"(c[0]), "+f"(c[1]), "+f"(c[2]), "+f"(c[3])
        : "r"(a[0]), "r"(a[1]), "r"(a[2]), "r"(a[3]), "r"(b0), "r"(b1));
}

// ========== K0: repack W_enc -> per-iter bf16 hi/lo tiles ==========
__global__ void k0_brepack(const float* __restrict__ W) {
    const int gid = blockIdx.x * 256 + threadIdx.x;    // NIT*64*16 = 188416
    if (gid >= NIT * 64 * 16) return;
    const int c   = gid & 15;
    const int row = (gid >> 4) & 63;
    const int it  = gid >> 10;
    const int k   = it * 32 + c * 2;
    const float v0 = (k < DIN)     ? W[row * DIN + k]     : 0.f;
    const float v1 = (k + 1 < DIN) ? W[row * DIN + k + 1] : 0.f;
    const uintT xh = cvt2(v0, v1);
    const float h0 = __uint_as_float(xh << 16);
    const float h1 = __uint_as_float(xh & 0xffff0000u);
    g_Bpkh[gid] = xh;
    g_Bpkl[gid] = cvt2(v0 - h0, v1 - h1);
}

// ========== K0b: transpose W_in -> [k][c] for coalesced k2 ==========
__global__ void k0b_wtr(const float* __restrict__ Win) {
    const int gid = blockIdx.x * 256 + threadIdx.x;    // 256*64 = 16384
    const int c = gid >> 6, k = gid & 63;
    g_WinT[k * 2 * DI + c] = Win[gid];
}

// ========== K1: encoder GEMM, bf16x3 MMA, k-split warps, DOUBLE-BUFFERED ==========
// C[16384,64] = A[16384,5881] @ W^T. BM=64, BN=64, BK=32, 256 thr (8 warps).
// Warp w: rows (w&3)*16, k-half s = w>>2. One __syncthreads per iter:
// stage(i+1) overlaps compute(i) on different pipes.
__global__ void __launch_bounds__(256) k1_gemm(const float* __restrict__ A,
                                               const float* __restrict__ be) {
    __shared__ __align__(16) ushortT sm2[2][4][2560];   // [buf][Ah,Al,Bh,Bl][64*40]

    const int tid  = threadIdx.x;
    const int lane = tid & 31, warp = tid >> 5;   // 0..7
    const int row0 = blockIdx.x * 64;
    const int s    = warp >> 2;                   // k-half
    const int mrow = (warp & 3) * 16;

    float w8[8];
    uint4 bqh, bql;

    auto loadR = [&](int it) {
        const int kb = it * 32;
        if (it < NIT - 1) {
#pragma unroll
            for (int i = 0; i < 8; i++)
                w8[i] = A[(size_t)(row0 + i * 8 + warp) * DIN + kb + lane];
        } else {
            const bool in = (kb + lane) < DIN;
#pragma unroll
            for (int i = 0; i < 8; i++)
                w8[i] = in ? A[(size_t)(row0 + i * 8 + warp) * DIN + kb + lane] : 0.f;
        }
        bqh = ((const uint4*)g_Bpkh)[it * 256 + tid];
        bql = ((const uint4*)g_Bpkl)[it * 256 + tid];
    };
    auto stage = [&](int buf) {
        ushortT* sAh = sm2[buf][0];
        ushortT* sAl = sm2[buf][1];
#pragma unroll
        for (int i = 0; i < 8; i++) {
            const float v = w8[i];
            const uintT xh = cvt2(v, 0.f);
            const float hf = __uint_as_float(xh << 16);
            const uintT xl = cvt2(v - hf, 0.f);
            sAh[(i * 8 + warp) * 40 + lane] = (ushortT)xh;
            sAl[(i * 8 + warp) * 40 + lane] = (ushortT)xl;
        }
        const int br = tid >> 2, bc = (tid & 3) * 16;
        *(uint4*)((char*)sm2[buf][2] + br * 80 + bc) = bqh;
        *(uint4*)((char*)sm2[buf][3] + br * 80 + bc) = bql;
    };

    float acc[8][4];
#pragma unroll
    for (int j = 0; j < 8; j++)
#pragma unroll
        for (int q = 0; q < 4; q++) acc[j][q] = 0.f;

    auto compute = [&](int buf) {
        const ushortT* sAh = sm2[buf][0];
        const ushortT* sAl = sm2[buf][1];
        const ushortT* sBh = sm2[buf][2];
        const ushortT* sBl = sm2[buf][3];
        uintT ah[4], al[4], bh[4], bl[4];
        const int aoff = (mrow + (lane & 15)) * 40 + 16 * s + ((lane >> 4) << 3);
        ldsm4(ah, sAh + aoff);
        ldsm4(al, sAl + aoff);
#pragma unroll
        for (int p = 0; p < 4; p++) {
            const int boff = (16 * p + ((lane >> 4) << 3) + (lane & 7)) * 40
                           + 16 * s + (lane & 8);
            ldsm4(bh, sBh + boff);
            ldsm4(bl, sBl + boff);
            mma16816(acc[2 * p],     ah, bh[0], bh[1]);
            mma16816(acc[2 * p],     ah, bl[0], bl[1]);
            mma16816(acc[2 * p],     al, bh[0], bh[1]);
            mma16816(acc[2 * p + 1], ah, bh[2], bh[3]);
            mma16816(acc[2 * p + 1], ah, bl[2], bl[3]);
            mma16816(acc[2 * p + 1], al, bh[2], bh[3]);
        }
    };

    loadR(0);
    stage(0);
    loadR(1);
    __syncthreads();                  // buf0 staged

    for (int it = 0; it < NIT; it++) {
        if (it + 1 < NIT) stage((it + 1) & 1);   // consumes regs (tile it+1)
        if (it + 2 < NIT) loadR(it + 2);          // prefetch tile it+2
        compute(it & 1);
        __syncthreads();   // stage(i+1) visible; compute(i) done before buf reuse
    }

    // epilogue: merge s=1 partials into s=0 warps via smem scratch (pitch 66)
    float* scr = (float*)sm2;
    const int r0 = mrow + (lane >> 2);
    const int cbase = (lane & 3) * 2;
    if (warp >= 4) {
#pragma unroll
        for (int j = 0; j < 8; j++) {
            const int c = 8 * j + cbase;
            *(float2*)&scr[r0 * 66 + c] = make_float2(acc[j][0], acc[j][1]);
            *(float2*)&scr[(r0 + 8) * 66 + c] = make_float2(acc[j][2], acc[j][3]);
        }
    }
    __syncthreads();
    if (warp < 4) {
#pragma unroll
        for (int j = 0; j < 8; j++) {
            const int c = 8 * j + cbase;
            const float2 p0 = *(const float2*)&scr[r0 * 66 + c];
            const float2 p1 = *(const float2*)&scr[(r0 + 8) * 66 + c];
            const float b0 = __ldg(be + c), b1 = __ldg(be + c + 1);
            *(float2*)&g_z[(row0 + r0) * DM + c] =
                make_float2(acc[j][0] + p0.x + b0, acc[j][1] + p0.y + b1);
            *(float2*)&g_z[(row0 + r0 + 8) * DM + c] =
                make_float2(acc[j][2] + p1.x + b0, acc[j][3] + p1.y + b1);
        }
    }
}

// ========== K2: in-proj + silu(gate), coalesced via WinT ==========
__global__ void k2_inproj() {
    __shared__ float zs[8][64];
    const int tid = threadIdx.x, row0 = blockIdx.x * 8;
#pragma unroll
    for (int it = 0; it < 2; it++) {
        const int f = tid + it * 256;
        zs[f >> 6][f & 63] = g_z[(row0 + (f >> 6)) * DM + (f & 63)];
    }
    __syncthreads();
    const int c = tid;
    float acc[8];
#pragma unroll
    for (int rr = 0; rr < 8; rr++) acc[rr] = 0.f;
#pragma unroll 8
    for (int k = 0; k < 64; k++) {
        const float wv = g_WinT[k * 2 * DI + c];
#pragma unroll
        for (int rr = 0; rr < 8; rr++) acc[rr] += zs[rr][k] * wv;
    }
#pragma unroll
    for (int rr = 0; rr < 8; rr++) {
        const int i = row0 + rr;
        if (c < DI) g_x[i * DI + c] = acc[rr];
        else        g_gates[i * DI + (c - DI)] = fsilu(acc[rr]);
    }
}

// ========== K3: causal depthwise conv(4) + silu ==========
__global__ void k3_conv(const float* __restrict__ cw, const float* __restrict__ cb) {
    const int gid = blockIdx.x * 256 + threadIdx.x;
    const int d = gid & 127, i = gid >> 7, t = i & 255;
    float s = cb[d];
#pragma unroll
    for (int k = 0; k < 4; k++) {
        const int tk = t + k - 3;
        if (tk >= 0) s += g_x[(i - t + tk) * DI + d] * cw[d * 4 + k];
    }
    g_xconv[gid] = fsilu(s);
}

// ========== K4: x-proj + dt path + B/C ==========
__global__ void k4_xproj(const float* __restrict__ Wx, const float* __restrict__ Wdt,
                         const float* __restrict__ bdt) {
    __shared__ float xs[16][129], Wxs[36][132], dbl[16][40], Wdts[DI * 4], bdts[DI];
    const int tid = threadIdx.x, row0 = blockIdx.x * 16;
    for (int f = tid; f < 36 * 128; f += 128) Wxs[f >> 7][f & 127] = Wx[f];
    for (int f = tid; f < DI * 4; f += 128) Wdts[f] = Wdt[f];
    if (tid < DI) bdts[tid] = bdt[tid];
    for (int f = tid; f < 16 * 128; f += 128)
        xs[f >> 7][f & 127] = g_xconv[(row0 + (f >> 7)) * DI + (f & 127)];
    __syncthreads();
    const int rr = tid >> 3, jg = tid & 7;
    float acc[5];
#pragma unroll
    for (int q = 0; q < 5; q++) acc[q] = 0.f;
#pragma unroll 4
    for (int k = 0; k < 128; k++) {
        const float xv = xs[rr][k];
#pragma unroll
        for (int q = 0; q < 5; q++) {
            const int j = jg + q * 8;
            if (j < 36) acc[q] += xv * Wxs[j][k];
        }
    }
#pragma unroll
    for (int q = 0; q < 5; q++) {
        const int j = jg + q * 8;
        if (j < 36) dbl[rr][j] = acc[q];
    }
    __syncthreads();
    {
        const int d = tid;
        const float w0 = Wdts[d * 4], w1 = Wdts[d * 4 + 1];
        const float w2 = Wdts[d * 4 + 2], w3 = Wdts[d * 4 + 3];
        const float bb = bdts[d];
#pragma unroll
        for (int q = 0; q < 16; q++) {
            float v = bb + dbl[q][0] * w0 + dbl[q][1] * w1 + dbl[q][2] * w2 + dbl[q][3] * w3;
            g_dt[(row0 + q) * DI + d] = fsoftplus(v);
        }
    }
    for (int f = tid; f < 16 * 32; f += 128) {
        const int q = f >> 5, c = f & 31;
        const float v = dbl[q][4 + c];
        if (c < 16) g_B[(row0 + q) * NS + c] = v;
        else        g_C[(row0 + q) * NS + (c - 16)] = v;
    }
}

// ========== K5: selective scan; exp(dt*A_n) = p^(n+1) fast path ==========
template <bool FAST>
__device__ __forceinline__ float scan_body(int b, int d, int half, int tid,
                                           const float* c2, float dsk, float* sBC) {
    float h[8];
#pragma unroll
    for (int n = 0; n < 8; n++) h[n] = 0.f;
    float ys = 0.f;
    for (int tc = 0; tc < 4; tc++) {
        __syncthreads();
#pragma unroll
        for (int it = 0; it < 16; it++) {
            const int f = tid + it * 128;
            const int tt = f >> 5, c = f & 31;
            const int i = b * TT + tc * 64 + tt;
            sBC[f] = (c < 16) ? g_B[i * NS + c] : g_C[i * NS + (c - 16)];
        }
        __syncthreads();
        for (int t = 0; t < 64; t++) {
            const int base = (b * TT + tc * 64 + t) * DI + d;
            const float dt = g_dt[base];
            const float xc = g_xconv[base];
            const float gg = g_gates[base];
            const float dtx = dt * xc;
            float e[8];
            if (FAST) {
                const float p = fexp2(-dt * LOG2E);
                if (half == 0) {
                    e[0] = p;
#pragma unroll
                    for (int n = 1; n < 8; n++) e[n] = e[n - 1] * p;
                } else {
                    const float p2 = p * p, p4 = p2 * p2, p8 = p4 * p4;
                    e[0] = p8 * p;
#pragma unroll
                    for (int n = 1; n < 8; n++) e[n] = e[n - 1] * p;
                }
            } else {
#pragma unroll
                for (int n = 0; n < 8; n++) e[n] = fexp2(dt * c2[n]);
            }
            const float* bc = &sBC[t * 32 + half * 8];
            float yp = 0.f;
#pragma unroll
            for (int n = 0; n < 8; n++) {
                h[n] = e[n] * h[n] + dtx * bc[n];
                yp += h[n] * bc[16 + n];
            }
            const float yo = yp + __shfl_xor_sync(0xffffffffu, yp, 1);
            ys += (yo + dsk * xc) * gg;
        }
    }
    return ys;
}

__global__ void k5_scan(const float* __restrict__ A_log, const float* __restrict__ Dskip) {
    __shared__ float sBC[64 * 32];
    const int tid = threadIdx.x;
    const int b = blockIdx.x >> 1, dbase = (blockIdx.x & 1) * 64;
    const int half = tid & 1;
    const int d = dbase + (tid >> 1);

    float c2[8];
    bool fast = true;
#pragma unroll
    for (int n = 0; n < 8; n++) {
        const float a = fexp(A_log[d * NS + half * 8 + n]);
        const float tgt = (float)(half * 8 + n + 1);
        if (fabsf(a - tgt) > 1e-3f * tgt) fast = false;
        c2[n] = -a * LOG2E;
    }
    fast = __all_sync(0xffffffffu, fast);
    const float dsk = Dskip[d];
    float ys = fast ? scan_body<true>(b, d, half, tid, c2, dsk, sBC)
                    : scan_body<false>(b, d, half, tid, c2, dsk, sBC);
    if (half == 0) g_ybar[b * DI + d] = ys * (1.f / 256.f);
}

// ========== K6: heads ==========
__global__ void k6_heads(const float* __restrict__ Wout,
                         const float* __restrict__ Wfc, const float* __restrict__ bfc,
                         const float* __restrict__ Wmu, const float* __restrict__ bmu,
                         const float* __restrict__ Wsig, const float* __restrict__ bsig,
                         float* __restrict__ out) {
    __shared__ float yb[DI], ev[DM], xsm[DI];
    const int b = blockIdx.x, tid = threadIdx.x;
    yb[tid] = g_ybar[b * DI + tid];
    __syncthreads();
    if (tid < DM) {
        float s = 0.f;
#pragma unroll 4
        for (int dd = 0; dd < DI; dd++) s += yb[dd] * Wout[tid * DI + dd];
        ev[tid] = s;
    }
    __syncthreads();
    {
        float v = bfc[tid];
#pragma unroll 4
        for (int m = 0; m < DM; m++) v += ev[m] * Wfc[tid * DM + m];
        const float t = tanhf(v);
        const float x = (t > 0.f) ? t : expm1f(t);
        xsm[tid] = x;
        out[b * DI + tid] = x;
    }
    __syncthreads();
    for (int o = tid; o < 256; o += 128) {
        float sm = bmu[o], sg = bsig[o];
#pragma unroll 4
        for (int l = 0; l < DI; l++) {
            const float xv = xsm[l];
            sm += xv * Wmu[o * DI + l];
            sg += xv * Wsig[o * DI + l];
        }
        out[NB * DI + b * 256 + o] = sm;
        const float e2 = (sg > 0.f) ? sg : expm1f(sg);
        out[NB * DI + NB * 256 + b * 256 + o] = e2 + 1.f + 1e-14f;
    }
}

extern "C" void kernel_launch(void* const* d_in, const int* in_sizes, int n_in,
                              void* d_out, int out_size) {
    const float* input  = (const float*)d_in[0];
    const float* W_enc  = (const float*)d_in[1];
    const float* b_enc  = (const float*)d_in[2];
    const float* W_in   = (const float*)d_in[3];
    const float* conv_w = (const float*)d_in[4];
    const float* conv_b = (const float*)d_in[5];
    const float* W_x    = (const float*)d_in[6];
    const float* W_dt   = (const float*)d_in[7];
    const float* b_dt   = (const float*)d_in[8];
    const float* A_log  = (const float*)d_in[9];
    const float* D_skip = (const float*)d_in[10];
    const float* W_out  = (const float*)d_in[11];
    const float* W_fc   = (const float*)d_in[12];
    const float* b_fc   = (const float*)d_in[13];
    const float* W_mu   = (const float*)d_in[14];
    const float* b_mu   = (const float*)d_in[15];
    const float* W_sig  = (const float*)d_in[16];
    const float* b_sig  = (const float*)d_in[17];
    float* out = (float*)d_out;

    k0_brepack<<<(NIT * 64 * 16 + 255) / 256, 256>>>(W_enc);
    k0b_wtr<<<(2 * DI * DM) / 256, 256>>>(W_in);
    k1_gemm<<<BT / 64, 256>>>(input, b_enc);
    k2_inproj<<<BT / 8, 256>>>();
    k3_conv<<<(BT * DI) / 256, 256>>>(conv_w, conv_b);
    k4_xproj<<<BT / 16, 128>>>(W_x, W_dt, b_dt);
    k5_scan<<<NB * 2, 128>>>(A_log, D_skip);
    k6_heads<<<NB, 128>>>(W_out, W_fc, b_fc, W_mu, b_mu, W_sig, b_sig, out);
}